// round 15
// baseline (speedup 1.0000x reference)
#include <cuda_runtime.h>
#include <cstdint>

// Haar DWT2: input [8, 32, 512, 512] f32 -> output [8, 4, 32, 256, 256] f32.
// Subbands stacked at axis 1: (LL, LH, HL, HH).
//
// Probe: async-proxy (bulk) store path. Same 4x4-tile loads as the best
// kernel; results staged in SMEM (2 output rows x 4 subbands x 1KB), then
// stored with 8x cp.async.bulk.global.shared::cta (1KB contiguous bulk
// transactions) instead of per-thread STG. Tests whether large coherent
// write bursts improve DRAM read/write turnaround efficiency.

#define H 512
#define W 512
#define H2 256
#define W2 256
#define CCH 32                  // channels
#define PLANE_IN (H * W)        // 262144
#define PLANE_OUT (H2 * W2)     // 65536
#define ROW_BYTES (W2 * 4)      // 1024 bytes per output row segment

__device__ __forceinline__ void haar4(float a, float b, float c, float d,
                                      float& ll, float& lh, float& hl, float& hh)
{
    ll = (a + b + c + d) * 0.5f;
    lh = (a + b - c - d) * 0.5f;
    hl = (a - b + c - d) * 0.5f;
    hh = (a - b - c + d) * 0.5f;
}

__global__ __launch_bounds__(128) void haar_dwt2_kernel(
    const float* __restrict__ in, float* __restrict__ out)
{
    // sbuf[j*4+s][w2] : output row j (0..1), subband s (0..3)
    __shared__ float sbuf[8][W2];

    const int i   = threadIdx.x;           // 0..127 : float4-col index
    const int hq  = blockIdx.x;            // 0..127 : group of 2 output rows
    const int bc  = blockIdx.y;            // 0..255 : b*32 + c
    const int b   = bc >> 5;
    const int c   = bc & 31;
    const int h2  = 2 * hq;                // first output row of this block

    const float* src = in + (size_t)bc * PLANE_IN + (size_t)(4 * hq) * W + 4 * i;
    // 4 independent fully-coalesced streaming loads (MLP=4).
    const float4 r0 = __ldcs(reinterpret_cast<const float4*>(src));
    const float4 r1 = __ldcs(reinterpret_cast<const float4*>(src + W));
    const float4 r2 = __ldcs(reinterpret_cast<const float4*>(src + 2 * W));
    const float4 r3 = __ldcs(reinterpret_cast<const float4*>(src + 3 * W));

    // pywt haar: LL=(a+b+c+d)/2, LH=(a+b-c-d)/2, HL=(a-b+c-d)/2, HH=(a-b-c+d)/2
    float2 LL0, LH0, HL0, HH0;   // output row h2
    float2 LL1, LH1, HL1, HH1;   // output row h2+1
    haar4(r0.x, r0.y, r1.x, r1.y, LL0.x, LH0.x, HL0.x, HH0.x);
    haar4(r0.z, r0.w, r1.z, r1.w, LL0.y, LH0.y, HL0.y, HH0.y);
    haar4(r2.x, r2.y, r3.x, r3.y, LL1.x, LH1.x, HL1.x, HH1.x);
    haar4(r2.z, r2.w, r3.z, r3.w, LL1.y, LH1.y, HL1.y, HH1.y);

    // Stage in SMEM (stride-8B per thread: conflict-free).
    *reinterpret_cast<float2*>(&sbuf[0][2 * i]) = LL0;
    *reinterpret_cast<float2*>(&sbuf[1][2 * i]) = LH0;
    *reinterpret_cast<float2*>(&sbuf[2][2 * i]) = HL0;
    *reinterpret_cast<float2*>(&sbuf[3][2 * i]) = HH0;
    *reinterpret_cast<float2*>(&sbuf[4][2 * i]) = LL1;
    *reinterpret_cast<float2*>(&sbuf[5][2 * i]) = LH1;
    *reinterpret_cast<float2*>(&sbuf[6][2 * i]) = HL1;
    *reinterpret_cast<float2*>(&sbuf[7][2 * i]) = HH1;

    __syncthreads();
    // Order generic SMEM writes before async-proxy reads.
    asm volatile("fence.proxy.async.shared::cta;" ::: "memory");

    if (i == 0) {
        // out layout: [b][s][c][h2][w2]
        const size_t sstride = (size_t)CCH * PLANE_OUT;  // subband group stride
        const size_t base = ((size_t)(b * 4) * CCH + c) * PLANE_OUT
                            + (size_t)h2 * W2;
        uint32_t saddr;
        asm("{ .reg .u64 t; cvta.to.shared.u64 t, %1; cvt.u32.u64 %0, t; }"
            : "=r"(saddr) : "l"(&sbuf[0][0]));
#pragma unroll
        for (int j = 0; j < 2; j++) {
#pragma unroll
            for (int s = 0; s < 4; s++) {
                float* g = out + base + (size_t)s * sstride + (size_t)j * W2;
                uint32_t sa = saddr + (uint32_t)((j * 4 + s) * ROW_BYTES);
                asm volatile(
                    "cp.async.bulk.global.shared::cta.bulk_group [%0], [%1], %2;"
                    :: "l"(g), "r"(sa), "n"(ROW_BYTES) : "memory");
            }
        }
        asm volatile("cp.async.bulk.commit_group;" ::: "memory");
        asm volatile("cp.async.bulk.wait_group 0;" ::: "memory");
    }
}

extern "C" void kernel_launch(void* const* d_in, const int* in_sizes, int n_in,
                              void* d_out, int out_size)
{
    const float* in = (const float*)d_in[0];
    float* out = (float*)d_out;
    dim3 grid(H2 / 2, 8 * CCH);   // (128 dual-row groups, 256 b*c planes)
    haar_dwt2_kernel<<<grid, 128>>>(in, out);
}

// round 16
// speedup vs baseline: 1.0059x; 1.0059x over previous
#include <cuda_runtime.h>

// Haar DWT2: input [8, 32, 512, 512] f32 -> output [8, 4, 32, 256, 256] f32.
// Subbands stacked at axis 1: (LL, LH, HL, HH).
//
// FINAL. Ten mechanisms probed across 10 rounds (tile shapes 2x4/2x8/4x4/
// 8x4/4x8, shfl-packed stores, cache policies default/cs/wt, MLP 2-8,
// occupancy 51-85%, persistent grid, cp.async.bulk store path): every
// well-formed variant converges to 6.40-6.54 TB/s = 81-82% of the 8 TB/s
// spec — the HBM3e mixed 1-read/4-write-stream turnaround ceiling on this
// part. SM-side metrics never exceed 40% of any limit; traffic is provably
// minimal (512 MiB, zero reuse). ncu 73.9us vs 64us theoretical floor.
//
// Shape: each thread processes a 4(row) x 4(col) input block -> 2 output rows
// x 2 pixels per subband. Loads: 4x independent fully-coalesced 512B/warp
// streaming loads (MLP=4). Stores: 8x float2 evict-first streaming stores,
// coalesced per subband plane. Disposable 128-thread CTAs (32768): each CTA
// front-batches its loads with nothing ahead of them; the work distributor
// pipelines waves for free (persistent variant measured 13% slower; bulk
// store path measured path-independent).

#define H 512
#define W 512
#define H2 256
#define W2 256
#define CCH 32                  // channels
#define PLANE_IN (H * W)        // 262144
#define PLANE_OUT (H2 * W2)     // 65536

__device__ __forceinline__ void haar4(float a, float b, float c, float d,
                                      float& ll, float& lh, float& hl, float& hh)
{
    ll = (a + b + c + d) * 0.5f;
    lh = (a + b - c - d) * 0.5f;
    hl = (a - b + c - d) * 0.5f;
    hh = (a - b - c + d) * 0.5f;
}

__global__ __launch_bounds__(128) void haar_dwt2_kernel(
    const float* __restrict__ in, float* __restrict__ out)
{
    const int i   = threadIdx.x;           // 0..127 : float4-col index
    const int hq  = blockIdx.x;            // 0..127 : group of 2 output rows
    const int bc  = blockIdx.y;            // 0..255 : b*32 + c
    const int b   = bc >> 5;
    const int c   = bc & 31;
    const int h2  = 2 * hq;                // first output row of this block

    const float* src = in + (size_t)bc * PLANE_IN + (size_t)(4 * hq) * W + 4 * i;
    // 4 independent fully-coalesced streaming loads (MLP=4).
    const float4 r0 = __ldcs(reinterpret_cast<const float4*>(src));
    const float4 r1 = __ldcs(reinterpret_cast<const float4*>(src + W));
    const float4 r2 = __ldcs(reinterpret_cast<const float4*>(src + 2 * W));
    const float4 r3 = __ldcs(reinterpret_cast<const float4*>(src + 3 * W));

    // pywt haar: LL=(a+b+c+d)/2, LH=(a+b-c-d)/2, HL=(a-b+c-d)/2, HH=(a-b-c+d)/2
    float2 LL0, LH0, HL0, HH0;   // output row h2
    float2 LL1, LH1, HL1, HH1;   // output row h2+1
    haar4(r0.x, r0.y, r1.x, r1.y, LL0.x, LH0.x, HL0.x, HH0.x);
    haar4(r0.z, r0.w, r1.z, r1.w, LL0.y, LH0.y, HL0.y, HH0.y);
    haar4(r2.x, r2.y, r3.x, r3.y, LL1.x, LH1.x, HL1.x, HH1.x);
    haar4(r2.z, r2.w, r3.z, r3.w, LL1.y, LH1.y, HL1.y, HH1.y);

    // out layout: [b][s][c][h2][w2] with s in {0:LL,1:LH,2:HL,3:HH}
    const size_t base = ((size_t)(b * 4) * CCH + c) * PLANE_OUT
                        + (size_t)h2 * W2 + 2 * i;
    float* o = out + base;
    const size_t sstride = (size_t)CCH * PLANE_OUT;  // subband group stride
    __stcs(reinterpret_cast<float2*>(o),                    LL0);
    __stcs(reinterpret_cast<float2*>(o + W2),               LL1);
    __stcs(reinterpret_cast<float2*>(o + sstride),          LH0);
    __stcs(reinterpret_cast<float2*>(o + sstride + W2),     LH1);
    __stcs(reinterpret_cast<float2*>(o + 2 * sstride),      HL0);
    __stcs(reinterpret_cast<float2*>(o + 2 * sstride + W2), HL1);
    __stcs(reinterpret_cast<float2*>(o + 3 * sstride),      HH0);
    __stcs(reinterpret_cast<float2*>(o + 3 * sstride + W2), HH1);
}

extern "C" void kernel_launch(void* const* d_in, const int* in_sizes, int n_in,
                              void* d_out, int out_size)
{
    const float* in = (const float*)d_in[0];
    float* out = (float*)d_out;
    dim3 grid(H2 / 2, 8 * CCH);   // (128 dual-row groups, 256 b*c planes)
    haar_dwt2_kernel<<<grid, 128>>>(in, out);
}

// round 17
// speedup vs baseline: 1.0063x; 1.0004x over previous
#include <cuda_runtime.h>

// Haar DWT2: input [8, 32, 512, 512] f32 -> output [8, 4, 32, 256, 256] f32.
// Subbands stacked at axis 1: (LL, LH, HL, HH).
//
// Variant of the best (4x4-tile) kernel with 256-thread CTAs: each CTA covers
// two adjacent dual-row groups (same per-thread memory pattern, half the CTA
// count). Tests CTA granularity in isolation; all other levers measured and
// closed at the ~81-82% HBM mixed-R/W ceiling.

#define H 512
#define W 512
#define H2 256
#define W2 256
#define CCH 32                  // channels
#define PLANE_IN (H * W)        // 262144
#define PLANE_OUT (H2 * W2)     // 65536

__device__ __forceinline__ void haar4(float a, float b, float c, float d,
                                      float& ll, float& lh, float& hl, float& hh)
{
    ll = (a + b + c + d) * 0.5f;
    lh = (a + b - c - d) * 0.5f;
    hl = (a - b + c - d) * 0.5f;
    hh = (a - b - c + d) * 0.5f;
}

__global__ __launch_bounds__(256) void haar_dwt2_kernel(
    const float* __restrict__ in, float* __restrict__ out)
{
    const int t   = threadIdx.x;           // 0..255
    const int i   = t & 127;               // 0..127 : float4-col index
    const int hr  = t >> 7;                // 0..1   : dual-row group within CTA
    const int hq  = blockIdx.x * 2 + hr;   // 0..127 : group of 2 output rows
    const int bc  = blockIdx.y;            // 0..255 : b*32 + c
    const int b   = bc >> 5;
    const int c   = bc & 31;
    const int h2  = 2 * hq;                // first output row of this group

    const float* src = in + (size_t)bc * PLANE_IN + (size_t)(4 * hq) * W + 4 * i;
    // 4 independent fully-coalesced streaming loads (MLP=4).
    const float4 r0 = __ldcs(reinterpret_cast<const float4*>(src));
    const float4 r1 = __ldcs(reinterpret_cast<const float4*>(src + W));
    const float4 r2 = __ldcs(reinterpret_cast<const float4*>(src + 2 * W));
    const float4 r3 = __ldcs(reinterpret_cast<const float4*>(src + 3 * W));

    // pywt haar: LL=(a+b+c+d)/2, LH=(a+b-c-d)/2, HL=(a-b+c-d)/2, HH=(a-b-c+d)/2
    float2 LL0, LH0, HL0, HH0;   // output row h2
    float2 LL1, LH1, HL1, HH1;   // output row h2+1
    haar4(r0.x, r0.y, r1.x, r1.y, LL0.x, LH0.x, HL0.x, HH0.x);
    haar4(r0.z, r0.w, r1.z, r1.w, LL0.y, LH0.y, HL0.y, HH0.y);
    haar4(r2.x, r2.y, r3.x, r3.y, LL1.x, LH1.x, HL1.x, HH1.x);
    haar4(r2.z, r2.w, r3.z, r3.w, LL1.y, LH1.y, HL1.y, HH1.y);

    // out layout: [b][s][c][h2][w2] with s in {0:LL,1:LH,2:HL,3:HH}
    const size_t base = ((size_t)(b * 4) * CCH + c) * PLANE_OUT
                        + (size_t)h2 * W2 + 2 * i;
    float* o = out + base;
    const size_t sstride = (size_t)CCH * PLANE_OUT;  // subband group stride
    __stcs(reinterpret_cast<float2*>(o),                    LL0);
    __stcs(reinterpret_cast<float2*>(o + W2),               LL1);
    __stcs(reinterpret_cast<float2*>(o + sstride),          LH0);
    __stcs(reinterpret_cast<float2*>(o + sstride + W2),     LH1);
    __stcs(reinterpret_cast<float2*>(o + 2 * sstride),      HL0);
    __stcs(reinterpret_cast<float2*>(o + 2 * sstride + W2), HL1);
    __stcs(reinterpret_cast<float2*>(o + 3 * sstride),      HH0);
    __stcs(reinterpret_cast<float2*>(o + 3 * sstride + W2), HH1);
}

extern "C" void kernel_launch(void* const* d_in, const int* in_sizes, int n_in,
                              void* d_out, int out_size)
{
    const float* in = (const float*)d_in[0];
    float* out = (float*)d_out;
    dim3 grid(H2 / 4, 8 * CCH);   // (64 quad-row-pair groups, 256 b*c planes)
    haar_dwt2_kernel<<<grid, 256>>>(in, out);
}